// round 8
// baseline (speedup 1.0000x reference)
#include <cuda_runtime.h>
#include <math.h>

#define NB 256
#define S  4096
#define FO 8
#define NM 64
#define FM 6
#define EPSF 1e-5f

#define PBLK 16     // proc stats sub-blocks per instance
#define OSB  4      // opes stats sub-blocks per instance
#define NPB  32     // proc norm sub-blocks per instance
#define OPB  8      // opes norm sub-blocks per instance

#define B_PSTAT 0                       // [0, 4096)   proc stats
#define B_OSTAT (NB * PBLK)             // [4096,5120) opes stats (+ mas stats)
#define B_PNORM (B_OSTAT + NB * OSB)    // [5120,13312) proc norm
#define B_ONORM (B_PNORM + NB * NPB)    // [13312,15360) opes norm (+ mas norm on sub0)
#define GRID_T  (B_ONORM + NB * OPB)

// -------- device scratch (fixed slots; flags self-reset each replay) --------
__device__ float g_part[NB][PBLK][4];        // proc partials: sum, sumsq, nnz
__device__ float g_opart[NB][OSB][2][FO];    // opes partials: sum, sumsq
__device__ float g_mmean[NB * FM];
__device__ float g_mrstd[NB * FM];
__device__ unsigned g_cnt[NB],  g_fin[NB];   // proc producer/consumer arrivals
__device__ unsigned g_ocnt[NB], g_ofin[NB];  // opes producer/consumer arrivals

__device__ __forceinline__ float warp_sum(float v) {
#pragma unroll
    for (int o = 16; o > 0; o >>= 1) v += __shfl_down_sync(0xffffffffu, v, o);
    return v;
}

// producer arrival: all block writes done (caller ensures sync), release then count
__device__ __forceinline__ void arrive(unsigned* cnt) {
    if (threadIdx.x == 0) { __threadfence(); atomicAdd(cnt, 1u); }
}

// consumer wait: thread0 spins on L1-bypassing load, fence, block-wide release
__device__ __forceinline__ void wait_for(unsigned* cnt, unsigned target) {
    if (threadIdx.x == 0) {
        volatile unsigned* p = (volatile unsigned*)cnt;
        while (*p < target) __nanosleep(32);
        __threadfence();
    }
    __syncthreads();
}

// consumer retire: last consumer resets both counters for the next graph replay
__device__ __forceinline__ void retire(unsigned* fin, unsigned* cnt, unsigned nCons) {
    if (threadIdx.x == 0) {
        unsigned o = atomicAdd(fin, 1u);
        if (o == nCons - 1) { *cnt = 0u; *fin = 0u; }
    }
}

__global__ void __launch_bounds__(256)
fusedAB_k(const float4* __restrict__ pt, float4* __restrict__ out_proc,
          const float* __restrict__ opes, float4* __restrict__ out_opes,
          const float* __restrict__ mas, float* __restrict__ out_mas,
          const int* __restrict__ nums) {
    const int bid = blockIdx.x;

    if (bid < B_OSTAT) {
        // ================= proc stats producer =================
        const int b   = bid >> 4;
        const int sub = bid & (PBLK - 1);
        const float4* src = pt + (size_t)b * (S * NM / 4) + (size_t)sub * 4096;

        float s = 0.f, ss = 0.f, c = 0.f;
        for (int i0 = threadIdx.x; i0 < 4096; i0 += 1024) {
            float4 v[4];
#pragma unroll
            for (int k = 0; k < 4; k++) v[k] = __ldcs(&src[i0 + k * 256]);
#pragma unroll
            for (int k = 0; k < 4; k++) {
                s  += (v[k].x + v[k].y) + (v[k].z + v[k].w);
                ss += (v[k].x * v[k].x + v[k].y * v[k].y) + (v[k].z * v[k].z + v[k].w * v[k].w);
                c  += (float)((v[k].x != 0.f) + (v[k].y != 0.f) + (v[k].z != 0.f) + (v[k].w != 0.f));
            }
        }
        __shared__ float sh2[3][8];
        int lane = threadIdx.x & 31, w = threadIdx.x >> 5;
        s = warp_sum(s); ss = warp_sum(ss); c = warp_sum(c);
        if (lane == 0) { sh2[0][w] = s; sh2[1][w] = ss; sh2[2][w] = c; }
        __syncthreads();
        if (threadIdx.x == 0) {
            float ts = 0.f, tss = 0.f, tc = 0.f;
#pragma unroll
            for (int i = 0; i < 8; i++) { ts += sh2[0][i]; tss += sh2[1][i]; tc += sh2[2][i]; }
            g_part[b][sub][0] = ts;
            g_part[b][sub][1] = tss;
            g_part[b][sub][2] = tc;
            __threadfence();
            atomicAdd(&g_cnt[b], 1u);
        }
    } else if (bid < B_PNORM) {
        // ================= opes stats producer (+ mas stats on sub0) =================
        const int ob  = bid - B_OSTAT;
        const int b   = ob >> 2;
        const int sub = ob & (OSB - 1);
        const int n   = nums[b];
        const int r0  = sub * 1024;
        const int r1  = min(r0 + 1024, n);

        float s[FO], q[FO];
#pragma unroll
        for (int f = 0; f < FO; f++) { s[f] = 0.f; q[f] = 0.f; }

        const float4* op = (const float4*)(opes + (size_t)b * S * FO);
        for (int r = r0 + threadIdx.x; r < r1; r += 256) {
            float4 a  = __ldcs(&op[r * 2]);
            float4 b4 = __ldcs(&op[r * 2 + 1]);
            float x[FO] = {a.x, a.y, a.z, a.w, b4.x, b4.y, b4.z, b4.w};
#pragma unroll
            for (int f = 0; f < FO; f++) { s[f] += x[f]; q[f] += x[f] * x[f]; }
        }
        __shared__ float sh[16][8];
        int lane = threadIdx.x & 31, w = threadIdx.x >> 5;
#pragma unroll
        for (int f = 0; f < FO; f++) {
            float rs = warp_sum(s[f]);
            float rq = warp_sum(q[f]);
            if (lane == 0) { sh[f][w] = rs; sh[f + 8][w] = rq; }
        }
        __syncthreads();
        if (threadIdx.x < FO) {
            int f = threadIdx.x;
            float ts = 0.f, tq = 0.f;
#pragma unroll
            for (int i = 0; i < 8; i++) { ts += sh[f][i]; tq += sh[f + 8][i]; }
            g_opart[b][sub][0][f] = ts;
            g_opart[b][sub][1][f] = tq;
        }
        if (sub == 0 && threadIdx.x >= 64 && threadIdx.x < 64 + FM) {
            int f = threadIdx.x - 64;
            const float* mp = mas + (size_t)b * NM * FM + f;
            float ts = 0.f, tq = 0.f;
#pragma unroll
            for (int m = 0; m < NM; m++) { float x = mp[m * FM]; ts += x; tq += x * x; }
            float fm   = (float)NM;
            float mean = ts / fm;
            float var  = (tq - ts * ts / fm) / (fm - 1.f);
            g_mmean[b * FM + f] = mean;
            g_mrstd[b * FM + f] = 1.f / (sqrtf(var) + EPSF);
        }
        __syncthreads();
        arrive(&g_ocnt[b]);
    } else if (bid < B_ONORM) {
        // ================= proc norm consumer =================
        const int pb  = bid - B_PNORM;
        const int b   = pb >> 5;
        const int sub = pb & (NPB - 1);

        wait_for(&g_cnt[b], PBLK);

        __shared__ float sm, sr;
        if (threadIdx.x < 32) {
            int lane = threadIdx.x;
            float s = 0.f, ss = 0.f, c = 0.f;
            if (lane < PBLK) {
                s  = g_part[b][lane][0];
                ss = g_part[b][lane][1];
                c  = g_part[b][lane][2];
            }
#pragma unroll
            for (int o = 8; o > 0; o >>= 1) {
                s  += __shfl_down_sync(0xffffffffu, s, o);
                ss += __shfl_down_sync(0xffffffffu, ss, o);
                c  += __shfl_down_sync(0xffffffffu, c, o);
            }
            if (lane == 0) {
                float m   = s / c;
                float var = (ss - s * s / c) / (c - 1.f);
                sm = m;
                sr = 1.f / (sqrtf(var) + EPSF);
            }
        }
        __syncthreads();
        retire(&g_fin[b], &g_cnt[b], NPB);
        const float m = sm, r = sr;

        const size_t base = (size_t)b * (S * NM / 4) + (size_t)sub * 2048;
        const float4* src = pt + base;
        float4*       dst = out_proc + base;
        for (int i0 = threadIdx.x; i0 < 2048; i0 += 512) {
            float4 v0 = __ldcs(&src[i0]);
            float4 v1 = __ldcs(&src[i0 + 256]);
            float4 o0, o1;
            o0.x = (v0.x != 0.f) ? (v0.x - m) * r : 0.f;
            o0.y = (v0.y != 0.f) ? (v0.y - m) * r : 0.f;
            o0.z = (v0.z != 0.f) ? (v0.z - m) * r : 0.f;
            o0.w = (v0.w != 0.f) ? (v0.w - m) * r : 0.f;
            o1.x = (v1.x != 0.f) ? (v1.x - m) * r : 0.f;
            o1.y = (v1.y != 0.f) ? (v1.y - m) * r : 0.f;
            o1.z = (v1.z != 0.f) ? (v1.z - m) * r : 0.f;
            o1.w = (v1.w != 0.f) ? (v1.w - m) * r : 0.f;
            __stcs(&dst[i0], o0);
            __stcs(&dst[i0 + 256], o1);
        }
    } else {
        // ================= opes norm consumer (+ mas norm on sub0) =================
        const int ob   = bid - B_ONORM;
        const int b    = ob >> 3;
        const int sub  = ob & (OPB - 1);
        const int base = b * 8192 + sub * 1024;

        wait_for(&g_ocnt[b], OSB);

        __shared__ float mm[FO], rr[FO];
        if (threadIdx.x < FO) {
            const int f = threadIdx.x;
            float ts = 0.f, tq = 0.f;
#pragma unroll
            for (int s2 = 0; s2 < OSB; s2++) {
                ts += g_opart[b][s2][0][f];
                tq += g_opart[b][s2][1][f];
            }
            float fn  = (float)nums[b];
            float mean = ts / fn;
            float var  = (tq - ts * ts / fn) / (fn - 1.f);
            mm[f] = mean;
            rr[f] = 1.f / (sqrtf(var) + EPSF);
        }
        __syncthreads();
        retire(&g_ofin[b], &g_ocnt[b], OPB);

        const float4* src = (const float4*)opes;
        for (int i0 = threadIdx.x; i0 < 1024; i0 += 512) {
            float4 v0 = __ldcs(&src[base + i0]);
            float4 v1 = __ldcs(&src[base + i0 + 256]);
            const float* M0 = &mm[(i0 & 1) * 4];
            const float* R0 = &rr[(i0 & 1) * 4];
            const float* M1 = &mm[((i0 + 256) & 1) * 4];
            const float* R1 = &rr[((i0 + 256) & 1) * 4];
            float4 o0, o1;
            o0.x = (v0.x - M0[0]) * R0[0];
            o0.y = (v0.y - M0[1]) * R0[1];
            o0.z = (v0.z - M0[2]) * R0[2];
            o0.w = (v0.w - M0[3]) * R0[3];
            o1.x = (v1.x - M1[0]) * R1[0];
            o1.y = (v1.y - M1[1]) * R1[1];
            o1.z = (v1.z - M1[2]) * R1[2];
            o1.w = (v1.w - M1[3]) * R1[3];
            __stcs(&out_opes[base + i0], o0);
            __stcs(&out_opes[base + i0 + 256], o1);
        }

        if (sub == 0) {
            // mas normalize for this instance: 384 floats (g_mmean written by opes sub0
            // stats producer, covered by the g_ocnt wait above)
            const float* min_ = mas + (size_t)b * NM * FM;
            float*       mout = out_mas + (size_t)b * NM * FM;
            for (int i = threadIdx.x; i < NM * FM; i += 256) {
                int f = i % FM;
                mout[i] = (min_[i] - g_mmean[b * FM + f]) * g_mrstd[b * FM + f];
            }
        }
    }
}

extern "C" void kernel_launch(void* const* d_in, const int* in_sizes, int n_in,
                              void* d_out, int out_size) {
    const float* raw_opes = (const float*)d_in[0];
    const float* raw_mas  = (const float*)d_in[1];
    const float* proc     = (const float*)d_in[2];
    const int*   nums     = (const int*)d_in[3];

    float* out_opes = (float*)d_out;
    float* out_mas  = out_opes + (size_t)NB * S * FO;
    float* out_proc = out_mas  + (size_t)NB * NM * FM;

    fusedAB_k<<<GRID_T, 256>>>((const float4*)proc, (float4*)out_proc,
                               raw_opes, (float4*)out_opes,
                               raw_mas, out_mas, nums);
}

// round 9
// speedup vs baseline: 1.1938x; 1.1938x over previous
#include <cuda_runtime.h>
#include <math.h>

#define NB 256
#define S  4096
#define FO 8
#define NM 64
#define FM 6
#define EPSF 1e-5f

#define PBLK 16     // proc stats sub-blocks per instance
#define OSB  4      // opes stats sub-blocks per instance
#define NPB  32     // proc norm sub-blocks per instance
#define OPB  8      // opes norm sub-blocks per instance
#define NSTAT (PBLK + OSB)     // 20
#define NNORM (NPB + OPB)      // 40
#define LEAD  16               // norm(b) dispatched alongside stats(b+LEAD)
#define GRID_T (NB * (NSTAT + NNORM))   // 15360

// -------- device scratch (fixed slots; flags self-reset each replay) --------
__device__ float g_part[NB][PBLK][4];
__device__ float g_opart[NB][OSB][2][FO];
__device__ float g_mmean[NB * FM];
__device__ float g_mrstd[NB * FM];
__device__ unsigned g_cnt[NB],  g_fin[NB];
__device__ unsigned g_ocnt[NB], g_ofin[NB];

__device__ __forceinline__ float warp_sum(float v) {
#pragma unroll
    for (int o = 16; o > 0; o >>= 1) v += __shfl_down_sync(0xffffffffu, v, o);
    return v;
}

__device__ __forceinline__ void wait_for(unsigned* cnt, unsigned target) {
    if (threadIdx.x == 0) {
        volatile unsigned* p = (volatile unsigned*)cnt;
        while (*p < target) __nanosleep(32);
        __threadfence();
    }
    __syncthreads();
}

__device__ __forceinline__ void retire(unsigned* fin, unsigned* cnt, unsigned nCons) {
    if (threadIdx.x == 0) {
        unsigned o = atomicAdd(fin, 1u);
        if (o == nCons - 1) { *cnt = 0u; *fin = 0u; }
    }
}

// ---------------- role bodies ----------------
__device__ void proc_stats(const float4* __restrict__ pt, int b, int sub) {
    const float4* src = pt + (size_t)b * (S * NM / 4) + (size_t)sub * 4096;
    float s = 0.f, ss = 0.f, c = 0.f;
    for (int i0 = threadIdx.x; i0 < 4096; i0 += 1024) {
        float4 v[4];
#pragma unroll
        for (int k = 0; k < 4; k++) v[k] = __ldcs(&src[i0 + k * 256]);
#pragma unroll
        for (int k = 0; k < 4; k++) {
            s  += (v[k].x + v[k].y) + (v[k].z + v[k].w);
            ss += (v[k].x * v[k].x + v[k].y * v[k].y) + (v[k].z * v[k].z + v[k].w * v[k].w);
            c  += (float)((v[k].x != 0.f) + (v[k].y != 0.f) + (v[k].z != 0.f) + (v[k].w != 0.f));
        }
    }
    __shared__ float sh[3][8];
    int lane = threadIdx.x & 31, w = threadIdx.x >> 5;
    s = warp_sum(s); ss = warp_sum(ss); c = warp_sum(c);
    if (lane == 0) { sh[0][w] = s; sh[1][w] = ss; sh[2][w] = c; }
    __syncthreads();
    if (threadIdx.x == 0) {
        float ts = 0.f, tss = 0.f, tc = 0.f;
#pragma unroll
        for (int i = 0; i < 8; i++) { ts += sh[0][i]; tss += sh[1][i]; tc += sh[2][i]; }
        g_part[b][sub][0] = ts;
        g_part[b][sub][1] = tss;
        g_part[b][sub][2] = tc;
        __threadfence();
        atomicAdd(&g_cnt[b], 1u);
    }
}

__device__ void opes_stats(const float* __restrict__ opes, const float* __restrict__ mas,
                           const int* __restrict__ nums, int b, int sub) {
    const int n  = nums[b];
    const int r0 = sub * 1024;
    const int r1 = min(r0 + 1024, n);

    float s[FO], q[FO];
#pragma unroll
    for (int f = 0; f < FO; f++) { s[f] = 0.f; q[f] = 0.f; }

    const float4* op = (const float4*)(opes + (size_t)b * S * FO);
    for (int r = r0 + threadIdx.x; r < r1; r += 256) {
        float4 a  = __ldcs(&op[r * 2]);
        float4 b4 = __ldcs(&op[r * 2 + 1]);
        float x[FO] = {a.x, a.y, a.z, a.w, b4.x, b4.y, b4.z, b4.w};
#pragma unroll
        for (int f = 0; f < FO; f++) { s[f] += x[f]; q[f] += x[f] * x[f]; }
    }
    __shared__ float sh[16][8];
    int lane = threadIdx.x & 31, w = threadIdx.x >> 5;
#pragma unroll
    for (int f = 0; f < FO; f++) {
        float rs = warp_sum(s[f]);
        float rq = warp_sum(q[f]);
        if (lane == 0) { sh[f][w] = rs; sh[f + 8][w] = rq; }
    }
    __syncthreads();
    if (threadIdx.x < FO) {
        int f = threadIdx.x;
        float ts = 0.f, tq = 0.f;
#pragma unroll
        for (int i = 0; i < 8; i++) { ts += sh[f][i]; tq += sh[f + 8][i]; }
        g_opart[b][sub][0][f] = ts;
        g_opart[b][sub][1][f] = tq;
    }
    if (sub == 0 && threadIdx.x >= 64 && threadIdx.x < 64 + FM) {
        int f = threadIdx.x - 64;
        const float* mp = mas + (size_t)b * NM * FM + f;
        float ts = 0.f, tq = 0.f;
#pragma unroll
        for (int m = 0; m < NM; m++) { float x = mp[m * FM]; ts += x; tq += x * x; }
        float fm   = (float)NM;
        float mean = ts / fm;
        float var  = (tq - ts * ts / fm) / (fm - 1.f);
        g_mmean[b * FM + f] = mean;
        g_mrstd[b * FM + f] = 1.f / (sqrtf(var) + EPSF);
    }
    __syncthreads();
    if (threadIdx.x == 0) { __threadfence(); atomicAdd(&g_ocnt[b], 1u); }
}

__device__ void proc_norm(const float4* __restrict__ pt, float4* __restrict__ out_proc,
                          int b, int sub) {
    wait_for(&g_cnt[b], PBLK);

    __shared__ float sm, sr;
    if (threadIdx.x < 32) {
        int lane = threadIdx.x;
        float s = 0.f, ss = 0.f, c = 0.f;
        if (lane < PBLK) {
            s  = g_part[b][lane][0];
            ss = g_part[b][lane][1];
            c  = g_part[b][lane][2];
        }
#pragma unroll
        for (int o = 8; o > 0; o >>= 1) {
            s  += __shfl_down_sync(0xffffffffu, s, o);
            ss += __shfl_down_sync(0xffffffffu, ss, o);
            c  += __shfl_down_sync(0xffffffffu, c, o);
        }
        if (lane == 0) {
            float m   = s / c;
            float var = (ss - s * s / c) / (c - 1.f);
            sm = m;
            sr = 1.f / (sqrtf(var) + EPSF);
        }
    }
    __syncthreads();
    retire(&g_fin[b], &g_cnt[b], NPB);
    const float m = sm, r = sr;

    const size_t base = (size_t)b * (S * NM / 4) + (size_t)sub * 2048;
    const float4* src = pt + base;
    float4*       dst = out_proc + base;
    for (int i0 = threadIdx.x; i0 < 2048; i0 += 512) {
        float4 v0 = __ldcs(&src[i0]);
        float4 v1 = __ldcs(&src[i0 + 256]);
        float4 o0, o1;
        o0.x = (v0.x != 0.f) ? (v0.x - m) * r : 0.f;
        o0.y = (v0.y != 0.f) ? (v0.y - m) * r : 0.f;
        o0.z = (v0.z != 0.f) ? (v0.z - m) * r : 0.f;
        o0.w = (v0.w != 0.f) ? (v0.w - m) * r : 0.f;
        o1.x = (v1.x != 0.f) ? (v1.x - m) * r : 0.f;
        o1.y = (v1.y != 0.f) ? (v1.y - m) * r : 0.f;
        o1.z = (v1.z != 0.f) ? (v1.z - m) * r : 0.f;
        o1.w = (v1.w != 0.f) ? (v1.w - m) * r : 0.f;
        __stcs(&dst[i0], o0);
        __stcs(&dst[i0 + 256], o1);
    }
}

__device__ void opes_norm(const float* __restrict__ opes, float4* __restrict__ out_opes,
                          const float* __restrict__ mas, float* __restrict__ out_mas,
                          const int* __restrict__ nums, int b, int sub) {
    const int base = b * 8192 + sub * 1024;

    wait_for(&g_ocnt[b], OSB);

    __shared__ float mm[FO], rr[FO];
    if (threadIdx.x < FO) {
        const int f = threadIdx.x;
        float ts = 0.f, tq = 0.f;
#pragma unroll
        for (int s2 = 0; s2 < OSB; s2++) {
            ts += g_opart[b][s2][0][f];
            tq += g_opart[b][s2][1][f];
        }
        float fn   = (float)nums[b];
        float mean = ts / fn;
        float var  = (tq - ts * ts / fn) / (fn - 1.f);
        mm[f] = mean;
        rr[f] = 1.f / (sqrtf(var) + EPSF);
    }
    __syncthreads();
    retire(&g_ofin[b], &g_ocnt[b], OPB);

    const float4* src = (const float4*)opes;
    for (int i0 = threadIdx.x; i0 < 1024; i0 += 512) {
        float4 v0 = __ldcs(&src[base + i0]);
        float4 v1 = __ldcs(&src[base + i0 + 256]);
        const float* M0 = &mm[(i0 & 1) * 4];
        const float* R0 = &rr[(i0 & 1) * 4];
        const float* M1 = &mm[((i0 + 256) & 1) * 4];
        const float* R1 = &rr[((i0 + 256) & 1) * 4];
        float4 o0, o1;
        o0.x = (v0.x - M0[0]) * R0[0];
        o0.y = (v0.y - M0[1]) * R0[1];
        o0.z = (v0.z - M0[2]) * R0[2];
        o0.w = (v0.w - M0[3]) * R0[3];
        o1.x = (v1.x - M1[0]) * R1[0];
        o1.y = (v1.y - M1[1]) * R1[1];
        o1.z = (v1.z - M1[2]) * R1[2];
        o1.w = (v1.w - M1[3]) * R1[3];
        __stcs(&out_opes[base + i0], o0);
        __stcs(&out_opes[base + i0 + 256], o1);
    }

    if (sub == 0) {
        const float* min_ = mas + (size_t)b * NM * FM;
        float*       mout = out_mas + (size_t)b * NM * FM;
        for (int i = threadIdx.x; i < NM * FM; i += 256) {
            int f = i % FM;
            mout[i] = (min_[i] - g_mmean[b * FM + f]) * g_mrstd[b * FM + f];
        }
    }
}

// ---------------- interleaved dispatch ----------------
// bid layout:
//   [0, LEAD*NSTAT)          : stats(b=0..LEAD-1)
//   [.., +(NB-LEAD)*(NSTAT+NNORM)) : per b in LEAD..NB-1: stats(b) then norm(b-LEAD)
//   tail                     : norm(b=NB-LEAD..NB-1)
__global__ void __launch_bounds__(256)
fusedAB_k(const float4* __restrict__ pt, float4* __restrict__ out_proc,
          const float* __restrict__ opes, float4* __restrict__ out_opes,
          const float* __restrict__ mas, float* __restrict__ out_mas,
          const int* __restrict__ nums) {
    const int bid = blockIdx.x;
    const int HEAD = LEAD * NSTAT;                              // 320
    const int MID  = HEAD + (NB - LEAD) * (NSTAT + NNORM);      // 320 + 14400 = 14720

    int b, sub, is_stats;
    if (bid < HEAD) {
        b = bid / NSTAT; sub = bid % NSTAT; is_stats = 1;
    } else if (bid < MID) {
        int t = bid - HEAD;
        int seg = t / (NSTAT + NNORM);
        int k   = t % (NSTAT + NNORM);
        if (k < NSTAT) { b = LEAD + seg; sub = k; is_stats = 1; }
        else           { b = seg;        sub = k - NSTAT; is_stats = 0; }
    } else {
        int t = bid - MID;
        b = (NB - LEAD) + t / NNORM; sub = t % NNORM; is_stats = 0;
    }

    if (is_stats) {
        if (sub < PBLK) proc_stats(pt, b, sub);
        else            opes_stats(opes, mas, nums, b, sub - PBLK);
    } else {
        if (sub < NPB)  proc_norm(pt, out_proc, b, sub);
        else            opes_norm(opes, out_opes, mas, out_mas, nums, b, sub - NPB);
    }
}

extern "C" void kernel_launch(void* const* d_in, const int* in_sizes, int n_in,
                              void* d_out, int out_size) {
    const float* raw_opes = (const float*)d_in[0];
    const float* raw_mas  = (const float*)d_in[1];
    const float* proc     = (const float*)d_in[2];
    const int*   nums     = (const int*)d_in[3];

    float* out_opes = (float*)d_out;
    float* out_mas  = out_opes + (size_t)NB * S * FO;
    float* out_proc = out_mas  + (size_t)NB * NM * FM;

    fusedAB_k<<<GRID_T, 256>>>((const float4*)proc, (float4*)out_proc,
                               raw_opes, (float4*)out_opes,
                               raw_mas, out_mas, nums);
}